// round 3
// baseline (speedup 1.0000x reference)
#include <cuda_runtime.h>

#define TT   128
#define BB   256
#define SIG  64
#define MET  32
#define HH   256
#define FF   16
#define KTOT 352          // 256 (h) + 64 (signal) + 32 (metmast)
#define NG   1024         // 4 gates * 256 cols
#define NCTA 128
#define NTHR 256
#define BPC  2            // batches per CTA

// ---------------- scratch (static device allocations only) ----------------
__device__ __align__(16) float g_U[KTOT * NG];      // packed [U_i|U_ste|U_c|U_o ; W_sig ; W_met]
__device__ __align__(16) float g_bias[NG];
__device__ __align__(16) float g_Ufre[KTOT * FF];
__device__ __align__(16) float g_bfre[FF];
__device__ __align__(16) float g_trig[TT * 32];     // per step: 16 cos then 16 sin
__device__ __align__(16) float g_h[BB * HH];
__device__ __align__(16) float g_Z[BB * NG];
__device__ unsigned g_bar_count;
__device__ unsigned g_bar_gen;

// ---------------- helpers ----------------
__device__ __forceinline__ float hsig(float x) {
    return __saturatef(fmaf(x, 0.16666667f, 0.5f));
}
__device__ __forceinline__ unsigned long long pack2(float x, float y) {
    unsigned long long r;
    asm("mov.b64 %0, {%1, %2};" : "=l"(r) : "f"(x), "f"(y));
    return r;
}
__device__ __forceinline__ void fma2(unsigned long long &d, unsigned long long a, unsigned long long b) {
    asm("fma.rn.f32x2 %0, %1, %2, %0;" : "+l"(d) : "l"(a), "l"(b));
}

__device__ __forceinline__ void grid_barrier(unsigned gen) {
    __syncthreads();
    if (threadIdx.x == 0) {
        __threadfence();   // make this CTA's global writes visible (emits CCTL.IVALL + membar)
        unsigned arr = atomicAdd(&g_bar_count, 1u);
        if (arr == NCTA - 1) {
            g_bar_count = 0;
            __threadfence();
            atomicExch(&g_bar_gen, gen);
        } else {
            unsigned cur;
            do {
                asm volatile("ld.global.acquire.gpu.u32 %0, [%1];" : "=r"(cur) : "l"(&g_bar_gen));
            } while (cur < gen);
        }
        __threadfence();   // invalidate L1 so post-barrier loads see other SMs' writes
    }
    __syncthreads();
}

// ---------------- pack kernel: build concatenated weights + trig + reset barrier ----------------
__global__ void pack_kernel(
    const float* __restrict__ Wi_s,  const float* __restrict__ Wste_s, const float* __restrict__ Wfre_s,
    const float* __restrict__ Wc_s,  const float* __restrict__ Wo_s,
    const float* __restrict__ Wi_m,  const float* __restrict__ Wste_m, const float* __restrict__ Wfre_m,
    const float* __restrict__ Wc_m,  const float* __restrict__ Wo_m,
    const float* __restrict__ Ui,    const float* __restrict__ bi,
    const float* __restrict__ Uste,  const float* __restrict__ bste,
    const float* __restrict__ Ufre,  const float* __restrict__ bfre,
    const float* __restrict__ Uc,    const float* __restrict__ bc,
    const float* __restrict__ Uo,    const float* __restrict__ bo)
{
    int idx0   = blockIdx.x * blockDim.x + threadIdx.x;
    int stride = gridDim.x * blockDim.x;

    for (int idx = idx0; idx < KTOT * NG; idx += stride) {
        int k = idx / NG, c = idx % NG;
        int g = c >> 8, j = c & 255;
        const float* U4[4]  = {Ui, Uste, Uc, Uo};
        const float* Ws4[4] = {Wi_s, Wste_s, Wc_s, Wo_s};
        const float* Wm4[4] = {Wi_m, Wste_m, Wc_m, Wo_m};
        float v;
        if (k < HH)            v = U4[g][k * HH + j];
        else if (k < HH + SIG) v = Ws4[g][(k - HH) * HH + j];
        else                   v = Wm4[g][(k - HH - SIG) * HH + j];
        g_U[idx] = v;
    }
    for (int idx = idx0; idx < KTOT * FF; idx += stride) {
        int k = idx / FF, f = idx % FF;
        float v;
        if (k < HH)            v = Ufre[k * FF + f];
        else if (k < HH + SIG) v = Wfre_s[(k - HH) * FF + f];
        else                   v = Wfre_m[(k - HH - SIG) * FF + f];
        g_Ufre[idx] = v;
    }
    for (int idx = idx0; idx < NG; idx += stride) {
        int g = idx >> 8, j = idx & 255;
        const float* b4[4] = {bi, bste, bc, bo};
        g_bias[idx] = b4[g][j];
    }
    for (int idx = idx0; idx < FF; idx += stride) g_bfre[idx] = bfre[idx];
    for (int idx = idx0; idx < TT * FF; idx += stride) {
        int t = idx / FF, f = idx % FF;
        // mimic reference: omega computed in fp32, trig evaluated accurately (double)
        float om = 6.2831854820251465f * (float)(t + 1) * ((float)f / 16.0f);
        double omd = (double)om;
        g_trig[t * 32 + f]      = (float)cos(omd);
        g_trig[t * 32 + 16 + f] = (float)sin(omd);
    }
    if (idx0 == 0) { g_bar_count = 0; g_bar_gen = 0; }
}

// ---------------- persistent recurrent kernel ----------------
__global__ void __launch_bounds__(NTHR, 1) sfm_kernel(
    const float* __restrict__ signal, const float* __restrict__ metmast,
    const float* __restrict__ Ua,     const float* __restrict__ ba,
    const float* __restrict__ Wp,     const float* __restrict__ bp,
    const float* __restrict__ fcw,    const float* __restrict__ fcb,
    float* __restrict__ out)
{
    extern __shared__ float sm[];
    float* S_re   = sm;                       // BPC*FF*HH = 8192
    float* S_im   = S_re + BPC * FF * HH;     // 8192
    float* h_s    = S_im + BPC * FF * HH;     // BPC*HH = 512
    float* hs     = h_s + BPC * HH;           // 32*34 = 1088 (A tile, [k][row], pad 34)
    float* us     = hs + 32 * 34;             // 32*64 = 2048 (U tile, [k][col])
    float* fre_s  = us + 2048;                // 32
    float* red    = fre_s + 32;               // 256
    float* trig_s = red + 256;                // 32

    const int tid   = threadIdx.x;
    const int ct    = blockIdx.x;
    const int bt    = ct & 7;            // 8 b-tiles of 32
    const int ctile = ct >> 3;           // 16 c-tiles of 64
    const int b0    = bt * 32;
    const int c0    = ctile * 64;
    const int ty    = tid >> 4;          // 0..15 -> rows ty*2, ty*2+1
    const int tx    = tid & 15;          // 0..15 -> cols tx*4..+4

    // init state
    for (int i = tid; i < BPC * FF * HH; i += NTHR) { S_re[i] = 0.f; S_im[i] = 0.f; }
    for (int i = tid; i < BPC * HH; i += NTHR) h_s[i] = 0.f;
    for (int lb = 0; lb < BPC; lb++) g_h[(ct * BPC + lb) * HH + tid] = 0.f;

    float ba_r = ba[tid];
    float ua_r[FF];
#pragma unroll
    for (int f = 0; f < FF; f++) ua_r[f] = Ua[f];

    unsigned gen = 0;
    grid_barrier(++gen);

    for (int t = 0; t < TT; t++) {
        // ================= GEMM phase: Z = bias + [h|xs|xm] @ [U;W] =================
        unsigned long long a00, a01, a10, a11;
        {
            float4 bv = *(const float4*)&g_bias[c0 + tx * 4];
            a00 = pack2(bv.x, bv.y); a01 = pack2(bv.z, bv.w);
            a10 = a00; a11 = a01;
        }
#pragma unroll 1
        for (int kb = 0; kb < 11; kb++) {
            // stage A tile (32 rows x 32 k), transposed into hs[k][row]
#pragma unroll
            for (int p = 0; p < 4; p++) {
                int idx = tid + p * NTHR;
                int r = idx >> 5, kl = idx & 31;
                int b = b0 + r;
                float v;
                if (kb < 8)       v = g_h[b * HH + kb * 32 + kl];
                else if (kb < 10) v = signal[(b * TT + t) * SIG + (kb - 8) * 32 + kl];
                else              v = metmast[(b * TT + t) * MET + kl];
                hs[kl * 34 + r] = v;
            }
            // stage U tile (32 k x 64 cols)
#pragma unroll
            for (int p = 0; p < 8; p++) {
                int idx = tid + p * NTHR;
                int kl = idx >> 6, cc = idx & 63;
                us[kl * 64 + cc] = g_U[(kb * 32 + kl) * NG + c0 + cc];
            }
            __syncthreads();
#pragma unroll
            for (int kl = 0; kl < 32; kl++) {
                float2 h2 = *(const float2*)&hs[kl * 34 + ty * 2];
                unsigned long long h00 = pack2(h2.x, h2.x);
                unsigned long long h11 = pack2(h2.y, h2.y);
                ulonglong2 uu = *(const ulonglong2*)&us[kl * 64 + tx * 4];
                fma2(a00, h00, uu.x); fma2(a01, h00, uu.y);
                fma2(a10, h11, uu.x); fma2(a11, h11, uu.y);
            }
            __syncthreads();
        }
        {
            unsigned long long* Z64 = (unsigned long long*)g_Z;
            int r = b0 + ty * 2;
            int cidx = (c0 + tx * 4) >> 1;
            Z64[r * 512 + cidx]           = a00;
            Z64[r * 512 + cidx + 1]       = a01;
            Z64[(r + 1) * 512 + cidx]     = a10;
            Z64[(r + 1) * 512 + cidx + 1] = a11;
        }
        grid_barrier(++gen);

        // ================= elementwise phase (own 2 batches, state in smem) =================
        if (tid < 32) trig_s[tid] = g_trig[t * 32 + tid];
        __syncthreads();

#pragma unroll 1
        for (int lb = 0; lb < BPC; lb++) {
            int b = ct * BPC + lb;
            // fre gate: hsig(bfre + [h|xs|xm] . Ufre)  -- 16 dots of length 352
            {
                int f = tid & 15, ch = tid >> 4;
                float s = 0.f;
                int k0 = ch * 22;   // 16 chunks * 22 = 352
#pragma unroll
                for (int q = 0; q < 22; q++) {
                    int k = k0 + q;
                    float av;
                    if (k < HH)            av = h_s[lb * HH + k];
                    else if (k < HH + SIG) av = signal[(b * TT + t) * SIG + (k - HH)];
                    else                   av = metmast[(b * TT + t) * MET + (k - HH - SIG)];
                    s = fmaf(av, g_Ufre[k * FF + f], s);
                }
                red[tid] = s;
                __syncthreads();
                if (tid < FF) {
                    float tot = g_bfre[tid];
#pragma unroll
                    for (int j = 0; j < 16; j++) tot += red[tid + 16 * j];
                    fre_s[lb * FF + tid] = hsig(tot);
                }
                __syncthreads();
            }
            // per-hidden update: thread tid = hidden index
            const float* Zb = &g_Z[b * NG];
            float xi   = Zb[tid];
            float xste = Zb[HH + tid];
            float xc   = Zb[2 * HH + tid];
            float xo   = Zb[3 * HH + tid];
            float ig  = hsig(xi);
            float ste = hsig(xste);
            float cg  = ig * tanhf(xc);
            float og  = hsig(xo);
            float acc = 0.f;
#pragma unroll
            for (int f = 0; f < FF; f++) {
                float fm = ste * fre_s[lb * FF + f];
                int sidx = (lb * FF + f) * HH + tid;
                float sr = fmaf(fm, S_re[sidx], cg * trig_s[f]);
                float si = fmaf(fm, S_im[sidx], cg * trig_s[16 + f]);
                S_re[sidx] = sr; S_im[sidx] = si;
                acc = fmaf(fmaf(sr, sr, si * si), ua_r[f], acc);
            }
            float a  = tanhf(acc + ba_r);
            float hn = og * a;
            h_s[lb * HH + tid] = hn;
            g_h[b * HH + tid]  = hn;
        }
        grid_barrier(++gen);
    }

    // ================= output: out[b] = ((h.Wp + bp) * fcw + fcb) =================
    for (int lb = 0; lb < BPC; lb++) {
        int b = ct * BPC + lb;
        red[tid] = h_s[lb * HH + tid] * Wp[tid];
        __syncthreads();
        for (int s = 128; s > 0; s >>= 1) {
            if (tid < s) red[tid] += red[tid + s];
            __syncthreads();
        }
        if (tid == 0) out[b] = fmaf(red[0] + bp[0], fcw[0], fcb[0]);
        __syncthreads();
    }
}

// ---------------- launch ----------------
extern "C" void kernel_launch(void* const* d_in, const int* in_sizes, int n_in,
                              void* d_out, int out_size) {
    const float* signal = (const float*)d_in[0];
    const float* metmast = (const float*)d_in[1];
    const float* Wi_s   = (const float*)d_in[2];
    const float* Wste_s = (const float*)d_in[3];
    const float* Wfre_s = (const float*)d_in[4];
    const float* Wc_s   = (const float*)d_in[5];
    const float* Wo_s   = (const float*)d_in[6];
    const float* Wi_m   = (const float*)d_in[7];
    const float* Wste_m = (const float*)d_in[8];
    const float* Wfre_m = (const float*)d_in[9];
    const float* Wc_m   = (const float*)d_in[10];
    const float* Wo_m   = (const float*)d_in[11];
    const float* Ui     = (const float*)d_in[12];
    const float* bi     = (const float*)d_in[13];
    const float* Uste   = (const float*)d_in[14];
    const float* bste   = (const float*)d_in[15];
    const float* Ufre   = (const float*)d_in[16];
    const float* bfre   = (const float*)d_in[17];
    const float* Uc     = (const float*)d_in[18];
    const float* bc     = (const float*)d_in[19];
    const float* Uo     = (const float*)d_in[20];
    const float* bo     = (const float*)d_in[21];
    const float* Ua     = (const float*)d_in[22];
    const float* ba     = (const float*)d_in[23];
    const float* Wp     = (const float*)d_in[24];
    const float* bp     = (const float*)d_in[25];
    const float* fcw    = (const float*)d_in[26];
    const float* fcb    = (const float*)d_in[27];
    float* out = (float*)d_out;

    static int smem_set = 0;
    const int SMEM_BYTES = 20352 * 4 + 512;   // ~81.9 KB dynamic smem
    if (!smem_set) {
        cudaFuncSetAttribute(sfm_kernel, cudaFuncAttributeMaxDynamicSharedMemorySize, SMEM_BYTES);
        smem_set = 1;
    }

    pack_kernel<<<64, 256>>>(Wi_s, Wste_s, Wfre_s, Wc_s, Wo_s,
                             Wi_m, Wste_m, Wfre_m, Wc_m, Wo_m,
                             Ui, bi, Uste, bste, Ufre, bfre, Uc, bc, Uo, bo);
    sfm_kernel<<<NCTA, NTHR, SMEM_BYTES>>>(signal, metmast, Ua, ba, Wp, bp, fcw, fcb, out);
}

// round 4
// speedup vs baseline: 1.5412x; 1.5412x over previous
#include <cuda_runtime.h>

#define TT   128
#define BB   256
#define SIG  64
#define MET  32
#define HH   256
#define FF   16
#define KTOT 352          // 256 (h) + 64 (signal) + 32 (metmast)
#define NG   1024         // 4 gates * 256 cols
#define NCTA 128
#define NTHR 256
#define BPC  2            // batches per CTA (elementwise ownership)

// ---------------- scratch (static device allocations only) ----------------
__device__ __align__(16) float g_U[KTOT * NG];      // packed [U_i|U_ste|U_c|U_o ; W_sig ; W_met]
__device__ __align__(16) float g_bias[NG];
__device__ __align__(16) float g_Ufre[KTOT * FF];
__device__ __align__(16) float g_bfre[FF];
__device__ __align__(16) float g_trig[TT * 32];     // per step: 16 cos then 16 sin
__device__ __align__(16) float g_h[BB * HH];
__device__ __align__(16) float g_Z[BB * NG];
__device__ unsigned g_bar_count;
__device__ unsigned g_bar_gen;

// ---------------- helpers ----------------
__device__ __forceinline__ float hsig(float x) {
    return __saturatef(fmaf(x, 0.16666667f, 0.5f));
}
__device__ __forceinline__ unsigned long long pack2(float x, float y) {
    unsigned long long r;
    asm("mov.b64 %0, {%1, %2};" : "=l"(r) : "f"(x), "f"(y));
    return r;
}
__device__ __forceinline__ void fma2(unsigned long long &d, unsigned long long a, unsigned long long b) {
    asm("fma.rn.f32x2 %0, %1, %2, %0;" : "+l"(d) : "l"(a), "l"(b));
}

// Grid barrier with release/acquire semantics only. All cross-CTA data goes
// through L2 (__ldcg/__stcg), so NO L1 invalidate (CCTL.IVALL) is needed —
// this keeps L1 warm across steps and makes the barrier cheap.
__device__ __forceinline__ void grid_barrier(unsigned gen) {
    __syncthreads();
    if (threadIdx.x == 0) {
        unsigned arr;
        asm volatile("atom.add.acq_rel.gpu.global.u32 %0, [%1], 1;"
                     : "=r"(arr) : "l"(&g_bar_count) : "memory");
        if (arr == NCTA - 1) {
            asm volatile("st.relaxed.gpu.global.u32 [%0], 0;"
                         :: "l"(&g_bar_count) : "memory");
            asm volatile("st.release.gpu.global.u32 [%0], %1;"
                         :: "l"(&g_bar_gen), "r"(gen) : "memory");
        } else {
            unsigned cur;
            do {
                asm volatile("ld.acquire.gpu.global.u32 %0, [%1];"
                             : "=r"(cur) : "l"(&g_bar_gen) : "memory");
            } while (cur < gen);
        }
    }
    __syncthreads();
}

// ---------------- pack kernel: build concatenated weights + trig + reset barrier ----------------
__global__ void pack_kernel(
    const float* __restrict__ Wi_s,  const float* __restrict__ Wste_s, const float* __restrict__ Wfre_s,
    const float* __restrict__ Wc_s,  const float* __restrict__ Wo_s,
    const float* __restrict__ Wi_m,  const float* __restrict__ Wste_m, const float* __restrict__ Wfre_m,
    const float* __restrict__ Wc_m,  const float* __restrict__ Wo_m,
    const float* __restrict__ Ui,    const float* __restrict__ bi,
    const float* __restrict__ Uste,  const float* __restrict__ bste,
    const float* __restrict__ Ufre,  const float* __restrict__ bfre,
    const float* __restrict__ Uc,    const float* __restrict__ bc,
    const float* __restrict__ Uo,    const float* __restrict__ bo)
{
    int idx0   = blockIdx.x * blockDim.x + threadIdx.x;
    int stride = gridDim.x * blockDim.x;

    for (int idx = idx0; idx < KTOT * NG; idx += stride) {
        int k = idx / NG, c = idx % NG;
        int g = c >> 8, j = c & 255;
        const float* U4[4]  = {Ui, Uste, Uc, Uo};
        const float* Ws4[4] = {Wi_s, Wste_s, Wc_s, Wo_s};
        const float* Wm4[4] = {Wi_m, Wste_m, Wc_m, Wo_m};
        float v;
        if (k < HH)            v = U4[g][k * HH + j];
        else if (k < HH + SIG) v = Ws4[g][(k - HH) * HH + j];
        else                   v = Wm4[g][(k - HH - SIG) * HH + j];
        g_U[idx] = v;
    }
    for (int idx = idx0; idx < KTOT * FF; idx += stride) {
        int k = idx / FF, f = idx % FF;
        float v;
        if (k < HH)            v = Ufre[k * FF + f];
        else if (k < HH + SIG) v = Wfre_s[(k - HH) * FF + f];
        else                   v = Wfre_m[(k - HH - SIG) * FF + f];
        g_Ufre[idx] = v;
    }
    for (int idx = idx0; idx < NG; idx += stride) {
        int g = idx >> 8, j = idx & 255;
        const float* b4[4] = {bi, bste, bc, bo};
        g_bias[idx] = b4[g][j];
    }
    for (int idx = idx0; idx < FF; idx += stride) g_bfre[idx] = bfre[idx];
    for (int idx = idx0; idx < TT * FF; idx += stride) {
        int t = idx / FF, f = idx % FF;
        float om = 6.2831854820251465f * (float)(t + 1) * ((float)f / 16.0f);
        double omd = (double)om;
        g_trig[t * 32 + f]      = (float)cos(omd);
        g_trig[t * 32 + 16 + f] = (float)sin(omd);
    }
    if (idx0 == 0) { g_bar_count = 0; g_bar_gen = 0; }
}

// ---------------- persistent recurrent kernel ----------------
// SMEM layout (floats):
#define SM_US    0                         // 352*64  = 22528 (persistent weight slice)
#define SM_UFRE  (SM_US   + KTOT * 64)     // 352*16  = 5632
#define SM_SRE   (SM_UFRE + KTOT * FF)     // 8192
#define SM_SIM   (SM_SRE  + BPC * FF * HH) // 8192
#define SM_HS    (SM_SIM  + BPC * FF * HH) // 512
#define SM_A     (SM_HS   + BPC * HH)      // 2*32*34 = 2176 (double-buffered A tile)
#define SM_TRIG  (SM_A    + 2 * 32 * 34)   // 128*32  = 4096 (full trig table)
#define SM_XS    (SM_TRIG + TT * 32)       // 192
#define SM_FRE   (SM_XS   + BPC * 96)      // 32
#define SM_RED   (SM_FRE  + 32)            // 256
#define SM_TOTAL (SM_RED  + 256)           // = 51872 floats

__global__ void __launch_bounds__(NTHR, 1) sfm_kernel(
    const float* __restrict__ signal, const float* __restrict__ metmast,
    const float* __restrict__ Ua,     const float* __restrict__ ba,
    const float* __restrict__ Wp,     const float* __restrict__ bp,
    const float* __restrict__ fcw,    const float* __restrict__ fcb,
    float* __restrict__ out)
{
    extern __shared__ float sm[];
    float* U_s    = sm + SM_US;
    float* Ufre_s = sm + SM_UFRE;
    float* S_re   = sm + SM_SRE;
    float* S_im   = sm + SM_SIM;
    float* h_s    = sm + SM_HS;
    float* hsA    = sm + SM_A;
    float* trig_a = sm + SM_TRIG;
    float* x_s    = sm + SM_XS;
    float* fre_s  = sm + SM_FRE;
    float* red    = sm + SM_RED;

    const int tid   = threadIdx.x;
    const int ct    = blockIdx.x;
    const int bt    = ct & 7;            // 8 b-tiles of 32
    const int ctile = ct >> 3;           // 16 c-tiles of 64
    const int b0    = bt * 32;
    const int c0    = ctile * 64;
    const int ty    = tid >> 4;          // rows ty*2, ty*2+1
    const int tx    = tid & 15;          // cols tx*4 .. +4

    // ---- persistent loads into smem ----
    for (int idx = tid; idx < KTOT * 64; idx += NTHR) {
        int k = idx >> 6, cc = idx & 63;
        U_s[idx] = g_U[k * NG + c0 + cc];
    }
    for (int idx = tid; idx < KTOT * FF; idx += NTHR) Ufre_s[idx] = g_Ufre[idx];
    for (int idx = tid; idx < TT * 32; idx += NTHR)   trig_a[idx] = g_trig[idx];

    // ---- state init ----
    for (int i = tid; i < BPC * FF * HH; i += NTHR) { S_re[i] = 0.f; S_im[i] = 0.f; }
    for (int i = tid; i < BPC * HH; i += NTHR) h_s[i] = 0.f;
#pragma unroll
    for (int lb = 0; lb < BPC; lb++) __stcg(&g_h[(ct * BPC + lb) * HH + tid], 0.f);

    float ba_r = ba[tid];
    float ua_r[FF];
#pragma unroll
    for (int f = 0; f < FF; f++) ua_r[f] = Ua[f];

    // bias for this thread's 4 output columns (constant across steps)
    unsigned long long binit0, binit1;
    {
        float4 bv = *(const float4*)&g_bias[c0 + tx * 4];
        binit0 = pack2(bv.x, bv.y); binit1 = pack2(bv.z, bv.w);
    }

    unsigned gen = 0;
    grid_barrier(++gen);

    for (int t = 0; t < TT; t++) {
        // ================= GEMM phase: Z = bias + [h|xs|xm] @ [U;W] =================
        unsigned long long a00 = binit0, a01 = binit1, a10 = binit0, a11 = binit1;

        float stg[4];
        // staging indices for this thread
        const int sr0 = tid >> 5,            skl0 = tid & 31;           // p=0
        // (p>0 handled generically)
        // prologue: load + store k-block 0
        {
#pragma unroll
            for (int p = 0; p < 4; p++) {
                int idx = tid + p * NTHR;
                int r = idx >> 5, kl = idx & 31;
                stg[p] = __ldcg(&g_h[(b0 + r) * HH + kl]);      // kb=0
            }
#pragma unroll
            for (int p = 0; p < 4; p++) {
                int idx = tid + p * NTHR;
                int r = idx >> 5, kl = idx & 31;
                hsA[kl * 34 + r] = stg[p];
            }
        }
        __syncthreads();
        (void)sr0; (void)skl0;

#pragma unroll 1
        for (int kb = 0; kb < 11; kb++) {
            // prefetch next block into registers (overlaps with compute below)
            if (kb < 10) {
                int kn = kb + 1;
#pragma unroll
                for (int p = 0; p < 4; p++) {
                    int idx = tid + p * NTHR;
                    int r = idx >> 5, kl = idx & 31;
                    int b = b0 + r;
                    if (kn < 8)       stg[p] = __ldcg(&g_h[b * HH + kn * 32 + kl]);
                    else if (kn < 10) stg[p] = signal[(b * TT + t) * SIG + (kn - 8) * 32 + kl];
                    else              stg[p] = metmast[(b * TT + t) * MET + kl];
                }
            }
            // compute current block from smem
            const float* hb = &hsA[(kb & 1) * 1088];
            const float* ub = &U_s[kb * 32 * 64];
#pragma unroll
            for (int kl = 0; kl < 32; kl++) {
                float2 h2 = *(const float2*)&hb[kl * 34 + ty * 2];
                unsigned long long h00 = pack2(h2.x, h2.x);
                unsigned long long h11 = pack2(h2.y, h2.y);
                ulonglong2 uu = *(const ulonglong2*)&ub[kl * 64 + tx * 4];
                fma2(a00, h00, uu.x); fma2(a01, h00, uu.y);
                fma2(a10, h11, uu.x); fma2(a11, h11, uu.y);
            }
            if (kb < 10) {
                float* hn = &hsA[((kb + 1) & 1) * 1088];
#pragma unroll
                for (int p = 0; p < 4; p++) {
                    int idx = tid + p * NTHR;
                    int r = idx >> 5, kl = idx & 31;
                    hn[kl * 34 + r] = stg[p];
                }
                __syncthreads();
            }
        }
        // write Z tile to L2 (bypass L1 — consumed by other CTAs)
        {
            int r = b0 + ty * 2;
            unsigned long long* p0 = (unsigned long long*)&g_Z[r * NG + c0 + tx * 4];
            unsigned long long* p1 = (unsigned long long*)&g_Z[(r + 1) * NG + c0 + tx * 4];
            asm volatile("st.global.cg.v2.u64 [%0], {%1, %2};" :: "l"(p0), "l"(a00), "l"(a01) : "memory");
            asm volatile("st.global.cg.v2.u64 [%0], {%1, %2};" :: "l"(p1), "l"(a10), "l"(a11) : "memory");
        }
        grid_barrier(++gen);

        // ================= elementwise phase (own 2 batches, state in smem) =================
        // stage own-batch inputs for the fre gate
        if (tid < BPC * 96) {
            int lb = tid / 96, j = tid - lb * 96;
            int b = ct * BPC + lb;
            x_s[tid] = (j < SIG) ? signal[(b * TT + t) * SIG + j]
                                 : metmast[(b * TT + t) * MET + (j - SIG)];
        }
        __syncthreads();

        const float* tc = &trig_a[t * 32];

#pragma unroll 1
        for (int lb = 0; lb < BPC; lb++) {
            int b = ct * BPC + lb;
            // fre gate: hsig(bfre + [h|xs|xm] . Ufre)  -- 16 dots of length 352
            {
                int f = tid & 15, ch = tid >> 4;
                float s = 0.f;
                int k0 = ch * 22;   // 16 chunks * 22 = 352
#pragma unroll
                for (int q = 0; q < 22; q++) {
                    int k = k0 + q;
                    float av = (k < HH) ? h_s[lb * HH + k] : x_s[lb * 96 + (k - HH)];
                    s = fmaf(av, Ufre_s[k * FF + f], s);
                }
                red[tid] = s;
                __syncthreads();
                if (tid < FF) {
                    float tot = g_bfre[tid];
#pragma unroll
                    for (int j = 0; j < 16; j++) tot += red[tid + 16 * j];
                    fre_s[lb * FF + tid] = hsig(tot);
                }
                __syncthreads();
            }
            // per-hidden update: thread tid = hidden index
            const float* Zb = &g_Z[b * NG];
            float xi   = __ldcg(&Zb[tid]);
            float xste = __ldcg(&Zb[HH + tid]);
            float xc   = __ldcg(&Zb[2 * HH + tid]);
            float xo   = __ldcg(&Zb[3 * HH + tid]);
            float ig  = hsig(xi);
            float ste = hsig(xste);
            float cg  = ig * tanhf(xc);
            float og  = hsig(xo);
            float acc = 0.f;
#pragma unroll
            for (int f = 0; f < FF; f++) {
                float fm = ste * fre_s[lb * FF + f];
                int sidx = (lb * FF + f) * HH + tid;
                float sr = fmaf(fm, S_re[sidx], cg * tc[f]);
                float si = fmaf(fm, S_im[sidx], cg * tc[16 + f]);
                S_re[sidx] = sr; S_im[sidx] = si;
                acc = fmaf(fmaf(sr, sr, si * si), ua_r[f], acc);
            }
            float a  = tanhf(acc + ba_r);
            float hn = og * a;
            h_s[lb * HH + tid] = hn;
            __stcg(&g_h[b * HH + tid], hn);
        }
        grid_barrier(++gen);
    }

    // ================= output: out[b] = ((h.Wp + bp) * fcw + fcb) =================
    for (int lb = 0; lb < BPC; lb++) {
        int b = ct * BPC + lb;
        red[tid] = h_s[lb * HH + tid] * Wp[tid];
        __syncthreads();
        for (int s = 128; s > 0; s >>= 1) {
            if (tid < s) red[tid] += red[tid + s];
            __syncthreads();
        }
        if (tid == 0) out[b] = fmaf(red[0] + bp[0], fcw[0], fcb[0]);
        __syncthreads();
    }
}

// ---------------- launch ----------------
extern "C" void kernel_launch(void* const* d_in, const int* in_sizes, int n_in,
                              void* d_out, int out_size) {
    const float* signal = (const float*)d_in[0];
    const float* metmast = (const float*)d_in[1];
    const float* Wi_s   = (const float*)d_in[2];
    const float* Wste_s = (const float*)d_in[3];
    const float* Wfre_s = (const float*)d_in[4];
    const float* Wc_s   = (const float*)d_in[5];
    const float* Wo_s   = (const float*)d_in[6];
    const float* Wi_m   = (const float*)d_in[7];
    const float* Wste_m = (const float*)d_in[8];
    const float* Wfre_m = (const float*)d_in[9];
    const float* Wc_m   = (const float*)d_in[10];
    const float* Wo_m   = (const float*)d_in[11];
    const float* Ui     = (const float*)d_in[12];
    const float* bi     = (const float*)d_in[13];
    const float* Uste   = (const float*)d_in[14];
    const float* bste   = (const float*)d_in[15];
    const float* Ufre   = (const float*)d_in[16];
    const float* bfre   = (const float*)d_in[17];
    const float* Uc     = (const float*)d_in[18];
    const float* bc     = (const float*)d_in[19];
    const float* Uo     = (const float*)d_in[20];
    const float* bo     = (const float*)d_in[21];
    const float* Ua     = (const float*)d_in[22];
    const float* ba     = (const float*)d_in[23];
    const float* Wp     = (const float*)d_in[24];
    const float* bp     = (const float*)d_in[25];
    const float* fcw    = (const float*)d_in[26];
    const float* fcb    = (const float*)d_in[27];
    float* out = (float*)d_out;

    static int smem_set = 0;
    const int SMEM_BYTES = SM_TOTAL * 4;   // ~207.5 KB dynamic smem
    if (!smem_set) {
        cudaFuncSetAttribute(sfm_kernel, cudaFuncAttributeMaxDynamicSharedMemorySize, SMEM_BYTES);
        smem_set = 1;
    }

    pack_kernel<<<64, 256>>>(Wi_s, Wste_s, Wfre_s, Wc_s, Wo_s,
                             Wi_m, Wste_m, Wfre_m, Wc_m, Wo_m,
                             Ui, bi, Uste, bste, Ufre, bfre, Uc, bc, Uo, bo);
    sfm_kernel<<<NCTA, NTHR, SMEM_BYTES>>>(signal, metmast, Ua, ba, Wp, bp, fcw, fcb, out);
}